// round 2
// baseline (speedup 1.0000x reference)
#include <cuda_runtime.h>
#include <math.h>

// SpikeToCalciumDoubleExp: 1D FIR conv with kernel[j] = (a^{j+1} - b^{j+1})/scale,
// a = exp(-1/tau1), b = exp(-1/tau2). Implemented as two first-order IIR
// recurrences with finite-window correction:
//   A[s] = a*A[s-1] + a*u[s] - a^{K+1}*u[s-K]
//   B[s] = b*B[s-1] + b*u[s] - b^{K+1}*u[s-K]
//   out[t] = (A[s] - B[s]) / scale,  s = t + K - 1
// ~12 ops/output instead of 2*K=242. DRAM-bound by design.
//
// Each CTA (128 threads) handles one (row, tile) pair of C_CTA = 6016 outputs.
// Input tile staged in SMEM via coalesced float4 loads; each thread runs the
// recurrence over CTH = 47 consecutive outputs (odd stride -> conflict-free
// SMEM banks); outputs staged in SMEM then stored with coalesced float4.

#define THREADS 128
#define CTH 47                       // odd -> stride-47 words is bank-conflict-free
#define C_CTA (THREADS * CTH)        // 6016 outputs per CTA
#define SMEM_IN (C_CTA + 128)        // 6016 + (K-1=120) + pad; total static smem 48.6KB < 48KB+1K limit

__global__ __launch_bounds__(THREADS)
void stc_iir_kernel(const float* __restrict__ u, float* __restrict__ out,
                    float a, float b, float aK1, float bK1, float inv_scale,
                    int K, int T_in, int T_out, int tiles_per_row)
{
    __shared__ float s_in[SMEM_IN];
    __shared__ float s_out[C_CTA];

    const int tile = blockIdx.x % tiles_per_row;
    const int row  = blockIdx.x / tiles_per_row;
    const int t0   = tile * C_CTA;
    const float* __restrict__ urow = u + (long long)row * T_in;
    const int tid = threadIdx.x;

    // ---- Stage input tile [t0, t0 + C_CTA + K - 1) into SMEM, coalesced ----
    const int need = C_CTA + K - 1;
    if ((T_in & 3) == 0 && need + 3 < SMEM_IN + 4) {
        const int n4 = (need + 3) >> 2;
        #pragma unroll 4
        for (int i = tid; i < n4; i += THREADS) {
            const int l = i << 2;
            const int g = t0 + l;
            float4 v;
            if (g + 3 < T_in) {
                v = *(const float4*)(urow + g);
            } else {
                v.x = (g     < T_in) ? urow[g]     : 0.f;
                v.y = (g + 1 < T_in) ? urow[g + 1] : 0.f;
                v.z = (g + 2 < T_in) ? urow[g + 2] : 0.f;
                v.w = (g + 3 < T_in) ? urow[g + 3] : 0.f;
            }
            *(float4*)(s_in + l) = v;
        }
    } else {
        for (int l = tid; l < need && l < SMEM_IN; l += THREADS) {
            const int g = t0 + l;
            s_in[l] = (g < T_in) ? urow[g] : 0.f;
        }
    }
    __syncthreads();

    // ---- Per-thread recurrence over CTH consecutive outputs ----
    const int lt = tid * CTH;                    // local index of first output
    if (t0 + lt < T_out) {
        // Init A,B at s0 = lt + K - 1 via Horner (no weight table):
        //   after loop acc = sum_j a^j * s_in[lt+K-1-j]; then A = a * acc
        float A = 0.f, B = 0.f;
        const float* __restrict__ pi = s_in + lt;
        #pragma unroll 4
        for (int m = 0; m < K; ++m) {
            const float x = pi[m];
            A = fmaf(a, A, x);
            B = fmaf(b, B, x);
        }
        A *= a;
        B *= b;
        s_out[lt] = fmaf(A, inv_scale, -(B * inv_scale));

        const float* __restrict__ ps = s_in + lt + (K - 1);  // current input stream u[s]
        const float* __restrict__ pl = s_in + lt - 1;        // lagged stream u[s-K]
        #pragma unroll 4
        for (int i = 1; i < CTH; ++i) {
            const float xs = ps[i];
            const float xl = pl[i];
            A = fmaf(a, A, fmaf(-aK1, xl, a * xs));
            B = fmaf(b, B, fmaf(-bK1, xl, b * xs));
            s_out[lt + i] = fmaf(A, inv_scale, -(B * inv_scale));
        }
    }
    __syncthreads();

    // ---- Store output tile, coalesced ----
    float* __restrict__ orow = out + (long long)row * T_out;
    int nvalid = T_out - t0;
    if (nvalid > C_CTA) nvalid = C_CTA;
    if ((T_out & 3) == 0) {
        const int n4 = (nvalid + 3) >> 2;
        #pragma unroll 4
        for (int i = tid; i < n4; i += THREADS) {
            const int l = i << 2;
            if (l + 3 < nvalid) {
                *(float4*)(orow + t0 + l) = *(const float4*)(s_out + l);
            } else {
                #pragma unroll
                for (int k2 = 0; k2 < 4; ++k2)
                    if (l + k2 < nvalid) orow[t0 + l + k2] = s_out[l + k2];
            }
        }
    } else {
        for (int l = tid; l < nvalid; l += THREADS)
            orow[t0 + l] = s_out[l];
    }
}

extern "C" void kernel_launch(void* const* d_in, const int* in_sizes, int n_in,
                              void* d_out, int out_size)
{
    const float* u = (const float*)d_in[0];
    const int K = (n_in > 1) ? in_sizes[1] : 121;

    // rows * T_in = in_sizes[0]; rows * T_out = out_size; T_in - T_out = K - 1
    const long long total_in = (long long)in_sizes[0];
    int rows = 1;
    if (K > 1) {
        const long long diff = total_in - (long long)out_size;
        if (diff > 0 && diff % (K - 1) == 0) {
            const long long r = diff / (K - 1);
            if (r > 0 && total_in % r == 0 && out_size % r == 0) rows = (int)r;
        }
    }
    const int T_in  = (int)(total_in / rows);
    const int T_out = out_size / rows;

    // Constants from the reference formula (HZ=20, TAU1=1.0, TAU2=0.1)
    const double tau1 = 1.0 * 20.0;
    const double tau2 = 0.1 * 20.0;
    const double a = exp(-1.0 / tau1);
    const double b = exp(-1.0 / tau2);
    const double r = tau1 / tau2;
    const double d = tau1 - tau2;
    const double scale = pow(r, -tau2 / d) - pow(r, -tau1 / d);

    const float fa = (float)a;
    const float fb = (float)b;
    const float aK1 = (float)pow(a, (double)(K + 1));
    const float bK1 = (float)pow(b, (double)(K + 1));
    const float inv_scale = (float)(1.0 / scale);

    const int tiles = (T_out + C_CTA - 1) / C_CTA;

    stc_iir_kernel<<<rows * tiles, THREADS>>>(
        u, (float*)d_out, fa, fb, aK1, bK1, inv_scale,
        K, T_in, T_out, tiles);
}

// round 4
// speedup vs baseline: 1.5441x; 1.5441x over previous
#include <cuda_runtime.h>
#include <math.h>

// SpikeToCalciumDoubleExp: FIR conv, kernel[j] = (a^{j+1} - b^{j+1})/scale,
// computed as two first-order recurrences with finite-window (FIR) correction:
//   A[s] = a*A[s-1] + a*u[s] - a^{K+1}*u[s-K]     (slow exp, needs lag term)
//   B[s] = b*B[s-1] + b*u[s]                       (fast exp, b^{K+1} ~ 3e-27: lag dropped)
//   out  = A' - B'   (1/scale folded into the state coefficients)
//
// R3 -> R4: init Horner reassociated 4-way: dependent-FMA chain 121 -> 31
// (B: 28 -> 7). Tile CTH=25 keeps 8 CTAs/SM (25.5KB smem), 32 warps/SM.

#define THREADS 128
#define CTH 25                       // odd -> stride-25 SMEM reads are conflict-free
#define C_CTA (THREADS * CTH)        // 3200 outputs per CTA
#define SMEM_IN (C_CTA + 128)        // 3200 + (K-1) + pad = 3328
#define B_TRUNC 28                   // Horner terms for fast exponential (b^28 ~ 8e-7)

__global__ __launch_bounds__(THREADS, 8)
void stc_iir_kernel(const float* __restrict__ u, float* __restrict__ out,
                    float a, float b, float ia, float ib, float iaK1,
                    int K, int T_in, int T_out)
{
    __shared__ float s_in[SMEM_IN];
    __shared__ float s_out[C_CTA];

    const int tile = blockIdx.x;
    const int row  = blockIdx.y;
    const int t0   = tile * C_CTA;
    const float* __restrict__ urow = u + (long long)row * T_in;
    const int tid = threadIdx.x;

    // ---- Stage input tile [t0, t0 + C_CTA + K - 1) into SMEM, coalesced ----
    const int need = C_CTA + K - 1;
    if ((T_in & 3) == 0) {
        const int n4 = (need + 3) >> 2;
        #pragma unroll 2
        for (int i = tid; i < n4; i += THREADS) {
            const int l = i << 2;
            const int g = t0 + l;
            float4 v;
            if (g + 3 < T_in) {
                v = *(const float4*)(urow + g);
            } else {
                v.x = (g     < T_in) ? urow[g]     : 0.f;
                v.y = (g + 1 < T_in) ? urow[g + 1] : 0.f;
                v.z = (g + 2 < T_in) ? urow[g + 2] : 0.f;
                v.w = (g + 3 < T_in) ? urow[g + 3] : 0.f;
            }
            *(float4*)(s_in + l) = v;
        }
    } else {
        for (int l = tid; l < need && l < SMEM_IN; l += THREADS) {
            const int g = t0 + l;
            s_in[l] = (g < T_in) ? urow[g] : 0.f;
        }
    }
    __syncthreads();

    // ---- Per-thread recurrence over CTH consecutive outputs ----
    const int lt = tid * CTH;                    // local index of first output
    if (t0 + lt < T_out) {
        const float a2 = a * a,  a3 = a2 * a,  a4 = a2 * a2;
        const float b2 = b * b,  b3 = b2 * b,  b4 = b2 * b2;
        const float* __restrict__ pi = s_in + lt;

        // A-init: A = sum_{m=0}^{K-1} a^{K-1-m} x[m], 4-way reassociated Horner.
        // Remainder (K mod 4) handled serially first.
        float A = 0.f;
        const int ra = K & 3;
        #pragma unroll
        for (int m = 0; m < 4; ++m) {            // bounded; predicated by m < ra
            if (m < ra) A = fmaf(a, A, pi[m]);
        }
        #pragma unroll 4
        for (int m = ra; m < K; m += 4) {
            const float c = fmaf(a3, pi[m],
                            fmaf(a2, pi[m + 1],
                            fmaf(a,  pi[m + 2], pi[m + 3])));
            A = fmaf(a4, A, c);
        }

        // B-init: last B_TRUNC terms only (geometric decay), 4-way Horner.
        float B = 0.f;
        const int kb = (K > B_TRUNC) ? (K - B_TRUNC) : 0;
        const int rb = (K - kb) & 3;
        #pragma unroll
        for (int m = 0; m < 4; ++m) {
            if (m < rb) B = fmaf(b, B, pi[kb + m]);
        }
        #pragma unroll
        for (int m = kb + rb; m < K; m += 4) {
            const float c = fmaf(b3, pi[m],
                            fmaf(b2, pi[m + 1],
                            fmaf(b,  pi[m + 2], pi[m + 3])));
            B = fmaf(b4, B, c);
        }

        // Scaled states: A' = A_true/scale (Horner * a/scale), likewise B'.
        A *= ia;
        B *= ib;
        s_out[lt] = A - B;

        const float* __restrict__ ps = s_in + lt + (K - 1);  // u[s]
        const float* __restrict__ pl = s_in + lt - 1;        // u[s-K]
        #pragma unroll
        for (int i = 1; i < CTH; ++i) {
            const float xs = ps[i];
            const float xl = pl[i];
            A = fmaf(a, A, fmaf(-iaK1, xl, ia * xs));
            B = fmaf(b, B, ib * xs);
            s_out[lt + i] = A - B;
        }
    }
    __syncthreads();

    // ---- Store output tile, coalesced ----
    float* __restrict__ orow = out + (long long)row * T_out;
    int nvalid = T_out - t0;
    if (nvalid > C_CTA) nvalid = C_CTA;
    if ((T_out & 3) == 0) {
        const int n4 = (nvalid + 3) >> 2;
        #pragma unroll 2
        for (int i = tid; i < n4; i += THREADS) {
            const int l = i << 2;
            if (l + 3 < nvalid) {
                *(float4*)(orow + t0 + l) = *(const float4*)(s_out + l);
            } else {
                #pragma unroll
                for (int k2 = 0; k2 < 4; ++k2)
                    if (l + k2 < nvalid) orow[t0 + l + k2] = s_out[l + k2];
            }
        }
    } else {
        for (int l = tid; l < nvalid; l += THREADS)
            orow[t0 + l] = s_out[l];
    }
}

extern "C" void kernel_launch(void* const* d_in, const int* in_sizes, int n_in,
                              void* d_out, int out_size)
{
    const float* u = (const float*)d_in[0];
    const int K = (n_in > 1) ? in_sizes[1] : 121;

    // rows * T_in = in_sizes[0]; rows * T_out = out_size; T_in - T_out = K - 1
    const long long total_in = (long long)in_sizes[0];
    int rows = 1;
    if (K > 1) {
        const long long diff = total_in - (long long)out_size;
        if (diff > 0 && diff % (K - 1) == 0) {
            const long long r = diff / (K - 1);
            if (r > 0 && total_in % r == 0 && out_size % r == 0) rows = (int)r;
        }
    }
    const int T_in  = (int)(total_in / rows);
    const int T_out = out_size / rows;

    // Constants from the reference formula (HZ=20, TAU1=1.0, TAU2=0.1)
    const double tau1 = 1.0 * 20.0;
    const double tau2 = 0.1 * 20.0;
    const double a = exp(-1.0 / tau1);
    const double b = exp(-1.0 / tau2);
    const double r = tau1 / tau2;
    const double d = tau1 - tau2;
    const double scale = pow(r, -tau2 / d) - pow(r, -tau1 / d);
    const double inv = 1.0 / scale;

    const float fa   = (float)a;
    const float fb   = (float)b;
    const float ia   = (float)(a * inv);                       // a/scale
    const float ib   = (float)(b * inv);                       // b/scale
    const float iaK1 = (float)(pow(a, (double)(K + 1)) * inv); // a^{K+1}/scale

    const int tiles = (T_out + C_CTA - 1) / C_CTA;
    dim3 grid(tiles, rows);

    stc_iir_kernel<<<grid, THREADS>>>(
        u, (float*)d_out, fa, fb, ia, ib, iaK1, K, T_in, T_out);
}

// round 7
// speedup vs baseline: 1.7648x; 1.1429x over previous
#include <cuda_runtime.h>
#include <math.h>

// SpikeToCalciumDoubleExp via warp-parallel weighted scan (no shared memory).
//
// out[t] = A'[s] - B'[s],  s = t+K-1  (1/scale folded into both states)
//   A'[s] = a*A'[s-1] + ia*u[s] - iaK1*u[s-K]   (exact finite window)
//   B'[s] = b*B'[s-1] + ib*u[s]                  (b^{K+1} = e^{-61} ~ 3e-27: lag dropped)
//
// Each warp owns a SEG_LEN segment of one row. Per step: 128 consecutive
// outputs (4 per lane). Lane-local 4-tap Horner -> Kogge-Stone weighted scan
// across lanes (A: 5 steps, ratios a^4..a^64; B: 3 steps, first dropped
// weight b^32 = e^{-16} ~ 1.1e-7) -> carry apply (per-lane a^{4l}; b^{4l}
// truncated at lane>=8) -> 4-FMA intra-lane chain -> float4 STG from
// registers. Loads: one float4 for u[s], one float4 + 1 shuffle for the lag
// stream u[t-1..]. Segment-start carry = 32-lane cooperative weighted reduce
// over [t0, t0+K-2]; forcing lane0/step0 lag to 0 makes this exact for every
// segment (the u[t0-1] terms cancel identically) and avoids all OOB reads.

#define WARPS_PER_CTA 8
#define THREADS_SCAN (WARPS_PER_CTA * 32)
#define STEPS_PER_SEG 20
#define SEG_LEN (128 * STEPS_PER_SEG)   // 2560 outputs per warp segment

__device__ __forceinline__ void stc_step(
    const bool FIRST, const bool PARTIAL,
    const float* __restrict__ urow, float* __restrict__ orow,
    const int tb, const int t_end, const int lane, const int Km1,
    const float a, const float b, const float ia, const float ib, const float iaK1,
    const float mA1, const float mA2, const float mA4, const float mA8, const float mA16,
    const float nB1, const float nB2, const float nB4,
    const float a4l, const float b4l,
    float& carryA, float& carryB)
{
    const unsigned FULL = 0xffffffffu;
    const int tl = tb + 4 * lane;                 // first output t of this lane
    const bool v = !PARTIAL || (tl < t_end);      // t_end is 4-aligned -> whole quad valid

    float x0 = 0.f, x1 = 0.f, x2 = 0.f, x3 = 0.f;       // u[s] quad
    float y0 = 0.f, y1 = 0.f, y2 = 0.f, y3 = 0.f;       // lag quad u[t..t+3]
    if (v) {
        const float4 xv = *(const float4*)(urow + tl + Km1);
        x0 = xv.x; x1 = xv.y; x2 = xv.z; x3 = xv.w;
        const float4 yv = *(const float4*)(urow + tl);
        y0 = yv.x; y1 = yv.y; y2 = yv.z; y3 = yv.w;
    }
    // lag values l_j = u[t-1+j]: l0 = neighbor's y3; l1..l3 = y0..y2
    float l0 = __shfl_up_sync(FULL, y3, 1);
    if (lane == 0) l0 = FIRST ? 0.f : urow[tb - 1];

    const float ca0 = fmaf(ia, x0, -(iaK1 * l0));
    const float ca1 = fmaf(ia, x1, -(iaK1 * y0));
    const float ca2 = fmaf(ia, x2, -(iaK1 * y1));
    const float ca3 = fmaf(ia, x3, -(iaK1 * y2));
    const float cb0 = ib * x0, cb1 = ib * x1, cb2 = ib * x2, cb3 = ib * x3;

    // lane aggregates (Horner within lane)
    float SA = fmaf(a, fmaf(a, fmaf(a, ca0, ca1), ca2), ca3);
    float SB = fmaf(b, fmaf(b, fmaf(b, cb0, cb1), cb2), cb3);
    // inclusive Kogge-Stone weighted scan across lanes, chunk ratio a^4 (b^4)
    float t;
    t = __shfl_up_sync(FULL, SA, 1);  if (lane >= 1)  SA = fmaf(mA1,  t, SA);
    t = __shfl_up_sync(FULL, SA, 2);  if (lane >= 2)  SA = fmaf(mA2,  t, SA);
    t = __shfl_up_sync(FULL, SA, 4);  if (lane >= 4)  SA = fmaf(mA4,  t, SA);
    t = __shfl_up_sync(FULL, SA, 8);  if (lane >= 8)  SA = fmaf(mA8,  t, SA);
    t = __shfl_up_sync(FULL, SA, 16); if (lane >= 16) SA = fmaf(mA16, t, SA);
    t = __shfl_up_sync(FULL, SB, 1);  if (lane >= 1)  SB = fmaf(nB1,  t, SB);
    t = __shfl_up_sync(FULL, SB, 2);  if (lane >= 2)  SB = fmaf(nB2,  t, SB);
    t = __shfl_up_sync(FULL, SB, 4);  if (lane >= 4)  SB = fmaf(nB4,  t, SB);
    // exclusive
    float EA = __shfl_up_sync(FULL, SA, 1); EA = (lane >= 1) ? EA : 0.f;
    float EB = __shfl_up_sync(FULL, SB, 1); EB = (lane >= 1) ? EB : 0.f;

    // state entering this lane's chunk, then intra-lane chain
    const float PreA = fmaf(a4l, carryA, EA);
    const float PreB = fmaf(b4l, carryB, EB);
    const float A0 = fmaf(a, PreA, ca0);
    const float A1 = fmaf(a, A0, ca1);
    const float A2 = fmaf(a, A1, ca2);
    const float A3 = fmaf(a, A2, ca3);
    const float B0 = fmaf(b, PreB, cb0);
    const float B1 = fmaf(b, B0, cb1);
    const float B2 = fmaf(b, B1, cb2);
    const float B3 = fmaf(b, B2, cb3);

    carryA = __shfl_sync(FULL, A3, 31);
    carryB = __shfl_sync(FULL, B3, 31);

    if (v) {
        float4 o;
        o.x = A0 - B0; o.y = A1 - B1; o.z = A2 - B2; o.w = A3 - B3;
        *(float4*)(orow + tl) = o;
    }
}

__global__ __launch_bounds__(THREADS_SCAN)
void stc_scan_kernel(const float* __restrict__ u, float* __restrict__ out,
                     float a, float b, float ia, float ib, float iaK1, float inv_scale,
                     float l2a, float l2b,
                     int K, int T_in, int T_out, int segs_per_row, int total_segs)
{
    const int lane = threadIdx.x & 31;
    const int gseg = blockIdx.x * WARPS_PER_CTA + (threadIdx.x >> 5);
    if (gseg >= total_segs) return;
    const int row = gseg / segs_per_row;
    const int seg = gseg - row * segs_per_row;
    const int t0 = seg * SEG_LEN;
    const int t_end = min(t0 + SEG_LEN, T_out);
    const float* __restrict__ urow = u + (long long)row * T_in;
    float* __restrict__ orow = out + (long long)row * T_out;
    const int Km1 = K - 1;

    // scan/carry constants
    const float a2 = a * a, a4 = a2 * a2, b2 = b * b, b4 = b2 * b2;
    const float mA1 = a4, mA2 = a4 * a4, mA4 = mA2 * mA2, mA8 = mA4 * mA4, mA16 = mA8 * mA8;
    const float nB1 = b4, nB2 = b4 * b4, nB4 = nB2 * nB2;
    const float a4l = exp2f(l2a * (float)(4 * lane));
    const float b4l = (lane < 8) ? exp2f(l2b * (float)(4 * lane)) : 0.f;  // drops b^32 ~ 1e-7

    // ---- segment-start carry: inv_scale * sum_{i=0}^{K-2} p^{K-1-i} u[t0+i] ----
    float carryA, carryB;
    {
        const int i0 = 4 * lane;
        float Pa = 0.f, Pb = 0.f, wA = 0.f, wB = 0.f;
        if (i0 <= Km1 - 1) {
            float x0, x1 = 0.f, x2 = 0.f, x3 = 0.f;
            if (i0 + 3 <= Km1 - 1) {
                const float4 vv = *(const float4*)(urow + t0 + i0);
                x0 = vv.x; x1 = vv.y; x2 = vv.z; x3 = vv.w;
            } else {
                x0 = urow[t0 + i0];
                if (i0 + 1 <= Km1 - 1) x1 = urow[t0 + i0 + 1];
                if (i0 + 2 <= Km1 - 1) x2 = urow[t0 + i0 + 2];
            }
            Pa = fmaf(a, fmaf(a, fmaf(a, x0, x1), x2), x3);
            Pb = fmaf(b, fmaf(b, fmaf(b, x0, x1), x2), x3);
            wA = exp2f(l2a * (float)(K - 4 - i0)) * inv_scale;
            wB = exp2f(l2b * (float)(K - 4 - i0)) * inv_scale;
        }
        float qa = wA * Pa, qb = wB * Pb;
        #pragma unroll
        for (int k = 16; k >= 1; k >>= 1) {
            qa += __shfl_xor_sync(0xffffffffu, qa, k);
            qb += __shfl_xor_sync(0xffffffffu, qb, k);
        }
        carryA = qa; carryB = qb;
    }

    // ---- steps ----
    int tb = t0;
    if (tb + 128 <= t_end) {
        stc_step(true, false, urow, orow, tb, t_end, lane, Km1, a, b, ia, ib, iaK1,
                 mA1, mA2, mA4, mA8, mA16, nB1, nB2, nB4, a4l, b4l, carryA, carryB);
    } else {
        stc_step(true, true, urow, orow, tb, t_end, lane, Km1, a, b, ia, ib, iaK1,
                 mA1, mA2, mA4, mA8, mA16, nB1, nB2, nB4, a4l, b4l, carryA, carryB);
    }
    tb += 128;
    // unroll 2: lets ptxas hoist the next step's (address-independent) LDGs
    // above the current step's shuffle/FMA chain -> MLP 2 -> 4.
    #pragma unroll 2
    for (; tb + 128 <= t_end; tb += 128)
        stc_step(false, false, urow, orow, tb, t_end, lane, Km1, a, b, ia, ib, iaK1,
                 mA1, mA2, mA4, mA8, mA16, nB1, nB2, nB4, a4l, b4l, carryA, carryB);
    if (tb < t_end)
        stc_step(false, true, urow, orow, tb, t_end, lane, Km1, a, b, ia, ib, iaK1,
                 mA1, mA2, mA4, mA8, mA16, nB1, nB2, nB4, a4l, b4l, carryA, carryB);
}

// Correctness-only fallback for shapes the fast path doesn't cover.
__global__ void stc_fallback_kernel(const float* __restrict__ u, float* __restrict__ out,
                                    float a, float b, float inv_scale,
                                    int K, int T_in, int T_out, long long total)
{
    const long long idx = (long long)blockIdx.x * blockDim.x + threadIdx.x;
    if (idx >= total) return;
    const int row = (int)(idx / T_out);
    const int t   = (int)(idx - (long long)row * T_out);
    const float* p = u + (long long)row * T_in + t;
    float A = 0.f, B = 0.f;
    for (int m = 0; m < K; ++m) {
        const float x = p[m];
        A = fmaf(a, A, x);
        B = fmaf(b, B, x);
    }
    out[idx] = (a * A - b * B) * inv_scale;
}

extern "C" void kernel_launch(void* const* d_in, const int* in_sizes, int n_in,
                              void* d_out, int out_size)
{
    const float* u = (const float*)d_in[0];
    const int K = (n_in > 1) ? in_sizes[1] : 121;

    // rows * T_in = in_sizes[0]; rows * T_out = out_size; T_in - T_out = K - 1
    const long long total_in = (long long)in_sizes[0];
    int rows = 1;
    if (K > 1) {
        const long long diff = total_in - (long long)out_size;
        if (diff > 0 && diff % (K - 1) == 0) {
            const long long r = diff / (K - 1);
            if (r > 0 && total_in % r == 0 && out_size % r == 0) rows = (int)r;
        }
    }
    const int T_in  = (int)(total_in / rows);
    const int T_out = out_size / rows;

    // Constants from the reference formula (HZ=20, TAU1=1.0, TAU2=0.1)
    const double tau1 = 1.0 * 20.0;
    const double tau2 = 0.1 * 20.0;
    const double a = exp(-1.0 / tau1);
    const double b = exp(-1.0 / tau2);
    const double r = tau1 / tau2;
    const double d = tau1 - tau2;
    const double scale = pow(r, -tau2 / d) - pow(r, -tau1 / d);
    const double inv = 1.0 / scale;

    const float fa   = (float)a;
    const float fb   = (float)b;
    const float ia   = (float)(a * inv);                       // a/scale
    const float ib   = (float)(b * inv);                       // b/scale
    const float iaK1 = (float)(pow(a, (double)(K + 1)) * inv); // a^{K+1}/scale
    const float finv = (float)inv;
    const float l2a  = (float)(log(a) / log(2.0));
    const float l2b  = (float)(log(b) / log(2.0));

    const bool fast = (K >= 6) && ((K - 1) % 4 == 0) && (K - 1 <= 128) &&
                      (T_in % 4 == 0) && (T_out % 4 == 0);

    if (fast) {
        const int segs_per_row = (T_out + SEG_LEN - 1) / SEG_LEN;
        const int total_segs   = rows * segs_per_row;
        const int blocks = (total_segs + WARPS_PER_CTA - 1) / WARPS_PER_CTA;
        stc_scan_kernel<<<blocks, THREADS_SCAN>>>(
            u, (float*)d_out, fa, fb, ia, ib, iaK1, finv, l2a, l2b,
            K, T_in, T_out, segs_per_row, total_segs);
    } else {
        const long long total = (long long)rows * T_out;
        const int blocks = (int)((total + 255) / 256);
        stc_fallback_kernel<<<blocks, 256>>>(
            u, (float*)d_out, fa, fb, finv, K, T_in, T_out, total);
    }
}

// round 10
// speedup vs baseline: 2.3176x; 1.3132x over previous
#include <cuda_runtime.h>
#include <math.h>

// SpikeToCalciumDoubleExp via warp-parallel weighted scan (no shared memory).
//
// out[t] = A'[s] - B'[s],  s = t+K-1  (1/scale folded into both states)
//   A'[s] = a*A'[s-1] + ia*u[s] - iaK1*u[s-K]   (exact finite window)
//   B'[s] = b*B'[s-1] + ib*u[s]                  (b^{K+1} = e^{-61} ~ 3e-27: lag dropped)
//
// Radix-8 lanes: each step covers 256 outputs (8/lane). A-scan: 5 stages
// (ratios a^8..a^128; a^128 ~ 1.7e-3 NOT droppable). B-scan: 2 stages
// (dropped weight b^32 = e^{-16} ~ 1.1e-7); B carry factor truncated at
// lane >= 4. Lane Horner = two 4-chains + combine (depth 4, not 7).

#define WARPS_PER_CTA 8
#define THREADS_SCAN (WARPS_PER_CTA * 32)
#define STEP_OUT 256                    // outputs per warp step (8 per lane)
#define STEPS_PER_SEG 10
#define SEG_LEN (STEP_OUT * STEPS_PER_SEG)   // 2560 outputs per warp segment

__device__ __forceinline__ void stc_step8(
    const bool FIRST, const bool PARTIAL,
    const float* __restrict__ urow, float* __restrict__ orow,
    const int tb, const int t_end, const int lane, const int Km1,
    const float a, const float b, const float a4, const float b4,
    const float ia, const float ib, const float iaK1,
    const float mA1, const float mA2, const float mA4, const float mA8, const float mA16,
    const float nB1, const float nB2,
    const float a8l, const float b8l,
    float& carryA, float& carryB)
{
    const unsigned FULL = 0xffffffffu;
    const int tl = tb + 8 * lane;                 // first output t of this lane
    const bool v = !PARTIAL || (tl < t_end);      // T_out%8==0 -> whole 8-chunk valid

    float x0=0.f,x1=0.f,x2=0.f,x3=0.f,x4=0.f,x5=0.f,x6=0.f,x7=0.f;  // u[s]
    float y0=0.f,y1=0.f,y2=0.f,y3=0.f,y4=0.f,y5=0.f,y6=0.f,y7=0.f;  // u[t..]
    if (v) {
        const float4 xa = *(const float4*)(urow + tl + Km1);
        const float4 xb = *(const float4*)(urow + tl + Km1 + 4);
        x0=xa.x; x1=xa.y; x2=xa.z; x3=xa.w; x4=xb.x; x5=xb.y; x6=xb.z; x7=xb.w;
        const float4 ya = *(const float4*)(urow + tl);
        const float4 yb = *(const float4*)(urow + tl + 4);
        y0=ya.x; y1=ya.y; y2=ya.z; y3=ya.w; y4=yb.x; y5=yb.y; y6=yb.z; y7=yb.w;
    }
    // lag l_j = u[t-1+j]: l0 = prev lane's y7; l1..l7 = y0..y6
    float l0 = __shfl_up_sync(FULL, y7, 1);
    if (lane == 0) l0 = FIRST ? 0.f : urow[tb - 1];

    const float ca0 = fmaf(ia, x0, -(iaK1 * l0));
    const float ca1 = fmaf(ia, x1, -(iaK1 * y0));
    const float ca2 = fmaf(ia, x2, -(iaK1 * y1));
    const float ca3 = fmaf(ia, x3, -(iaK1 * y2));
    const float ca4 = fmaf(ia, x4, -(iaK1 * y3));
    const float ca5 = fmaf(ia, x5, -(iaK1 * y4));
    const float ca6 = fmaf(ia, x6, -(iaK1 * y5));
    const float ca7 = fmaf(ia, x7, -(iaK1 * y6));
    const float cb0 = ib*x0, cb1 = ib*x1, cb2 = ib*x2, cb3 = ib*x3;
    const float cb4 = ib*x4, cb5 = ib*x5, cb6 = ib*x6, cb7 = ib*x7;

    // lane aggregates: two 4-chains combined (depth 4, not 7)
    const float SAh = fmaf(a, fmaf(a, fmaf(a, ca0, ca1), ca2), ca3);
    const float SAl = fmaf(a, fmaf(a, fmaf(a, ca4, ca5), ca6), ca7);
    float SA = fmaf(a4, SAh, SAl);
    const float SBh = fmaf(b, fmaf(b, fmaf(b, cb0, cb1), cb2), cb3);
    const float SBl = fmaf(b, fmaf(b, fmaf(b, cb4, cb5), cb6), cb7);
    float SB = fmaf(b4, SBh, SBl);

    // inclusive Kogge-Stone weighted scan across lanes, chunk ratio a^8 (b^8)
    float t;
    t = __shfl_up_sync(FULL, SA, 1);  if (lane >= 1)  SA = fmaf(mA1,  t, SA);
    t = __shfl_up_sync(FULL, SA, 2);  if (lane >= 2)  SA = fmaf(mA2,  t, SA);
    t = __shfl_up_sync(FULL, SA, 4);  if (lane >= 4)  SA = fmaf(mA4,  t, SA);
    t = __shfl_up_sync(FULL, SA, 8);  if (lane >= 8)  SA = fmaf(mA8,  t, SA);
    t = __shfl_up_sync(FULL, SA, 16); if (lane >= 16) SA = fmaf(mA16, t, SA);
    t = __shfl_up_sync(FULL, SB, 1);  if (lane >= 1)  SB = fmaf(nB1,  t, SB);
    t = __shfl_up_sync(FULL, SB, 2);  if (lane >= 2)  SB = fmaf(nB2,  t, SB);
    // exclusive
    float EA = __shfl_up_sync(FULL, SA, 1); EA = (lane >= 1) ? EA : 0.f;
    float EB = __shfl_up_sync(FULL, SB, 1); EB = (lane >= 1) ? EB : 0.f;

    // state entering this lane's chunk, then intra-lane chains
    const float PreA = fmaf(a8l, carryA, EA);
    const float PreB = fmaf(b8l, carryB, EB);
    const float A0 = fmaf(a, PreA, ca0);
    const float A1 = fmaf(a, A0, ca1);
    const float A2 = fmaf(a, A1, ca2);
    const float A3 = fmaf(a, A2, ca3);
    const float A4 = fmaf(a, A3, ca4);
    const float A5 = fmaf(a, A4, ca5);
    const float A6 = fmaf(a, A5, ca6);
    const float A7 = fmaf(a, A6, ca7);
    const float B0 = fmaf(b, PreB, cb0);
    const float B1 = fmaf(b, B0, cb1);
    const float B2 = fmaf(b, B1, cb2);
    const float B3 = fmaf(b, B2, cb3);
    const float B4 = fmaf(b, B3, cb4);
    const float B5 = fmaf(b, B4, cb5);
    const float B6 = fmaf(b, B5, cb6);
    const float B7 = fmaf(b, B6, cb7);

    carryA = __shfl_sync(FULL, A7, 31);
    carryB = __shfl_sync(FULL, B7, 31);

    if (v) {
        float4 oa, ob;
        oa.x = A0 - B0; oa.y = A1 - B1; oa.z = A2 - B2; oa.w = A3 - B3;
        ob.x = A4 - B4; ob.y = A5 - B5; ob.z = A6 - B6; ob.w = A7 - B7;
        *(float4*)(orow + tl)     = oa;
        *(float4*)(orow + tl + 4) = ob;
    }
}

__global__ __launch_bounds__(THREADS_SCAN, 4)
void stc_scan_kernel(const float* __restrict__ u, float* __restrict__ out,
                     float a, float b, float ia, float ib, float iaK1, float inv_scale,
                     float l2a, float l2b,
                     int K, int T_in, int T_out, int segs_per_row, int total_segs)
{
    const int lane = threadIdx.x & 31;
    const int gseg = blockIdx.x * WARPS_PER_CTA + (threadIdx.x >> 5);
    if (gseg >= total_segs) return;
    const int row = gseg / segs_per_row;
    const int seg = gseg - row * segs_per_row;
    const int t0 = seg * SEG_LEN;
    const int t_end = min(t0 + SEG_LEN, T_out);
    const float* __restrict__ urow = u + (long long)row * T_in;
    float* __restrict__ orow = out + (long long)row * T_out;
    const int Km1 = K - 1;

    // scan/carry constants
    const float a2 = a*a, a4 = a2*a2, a8 = a4*a4, b2 = b*b, b4 = b2*b2, b8 = b4*b4;
    const float mA1 = a8, mA2 = a8*a8, mA4 = mA2*mA2, mA8 = mA4*mA4, mA16 = mA8*mA8;
    const float nB1 = b8, nB2 = b8*b8;                 // stage 3 dropped: b^32 ~ 1.1e-7
    const float a8l = exp2f(l2a * (float)(8 * lane));
    const float b8l = (lane < 4) ? exp2f(l2b * (float)(8 * lane)) : 0.f;

    // ---- segment-start carry: inv_scale * sum_{i=0}^{K-2} p^{K-1-i} u[t0+i] ----
    float carryA, carryB;
    {
        const int i0 = 4 * lane;
        float Pa = 0.f, Pb = 0.f, wA = 0.f, wB = 0.f;
        if (i0 <= Km1 - 1) {
            float x0, x1 = 0.f, x2 = 0.f, x3 = 0.f;
            if (i0 + 3 <= Km1 - 1) {
                const float4 vv = *(const float4*)(urow + t0 + i0);
                x0 = vv.x; x1 = vv.y; x2 = vv.z; x3 = vv.w;
            } else {
                x0 = urow[t0 + i0];
                if (i0 + 1 <= Km1 - 1) x1 = urow[t0 + i0 + 1];
                if (i0 + 2 <= Km1 - 1) x2 = urow[t0 + i0 + 2];
            }
            Pa = fmaf(a, fmaf(a, fmaf(a, x0, x1), x2), x3);
            Pb = fmaf(b, fmaf(b, fmaf(b, x0, x1), x2), x3);
            wA = exp2f(l2a * (float)(K - 4 - i0)) * inv_scale;
            wB = exp2f(l2b * (float)(K - 4 - i0)) * inv_scale;
        }
        float qa = wA * Pa, qb = wB * Pb;
        #pragma unroll
        for (int k = 16; k >= 1; k >>= 1) {
            qa += __shfl_xor_sync(0xffffffffu, qa, k);
            qb += __shfl_xor_sync(0xffffffffu, qb, k);
        }
        carryA = qa; carryB = qb;
    }

    // ---- steps ----
    int tb = t0;
    if (tb + STEP_OUT <= t_end) {
        stc_step8(true, false, urow, orow, tb, t_end, lane, Km1, a, b, a4, b4,
                  ia, ib, iaK1, mA1, mA2, mA4, mA8, mA16, nB1, nB2,
                  a8l, b8l, carryA, carryB);
    } else {
        stc_step8(true, true, urow, orow, tb, t_end, lane, Km1, a, b, a4, b4,
                  ia, ib, iaK1, mA1, mA2, mA4, mA8, mA16, nB1, nB2,
                  a8l, b8l, carryA, carryB);
    }
    tb += STEP_OUT;
    // unroll 2: lets ptxas hoist the next step's (address-independent) LDGs
    // above the current step's shuffle/FMA chain.
    #pragma unroll 2
    for (; tb + STEP_OUT <= t_end; tb += STEP_OUT)
        stc_step8(false, false, urow, orow, tb, t_end, lane, Km1, a, b, a4, b4,
                  ia, ib, iaK1, mA1, mA2, mA4, mA8, mA16, nB1, nB2,
                  a8l, b8l, carryA, carryB);
    if (tb < t_end)
        stc_step8(false, true, urow, orow, tb, t_end, lane, Km1, a, b, a4, b4,
                  ia, ib, iaK1, mA1, mA2, mA4, mA8, mA16, nB1, nB2,
                  a8l, b8l, carryA, carryB);
}

// Correctness-only fallback for shapes the fast path doesn't cover.
__global__ void stc_fallback_kernel(const float* __restrict__ u, float* __restrict__ out,
                                    float a, float b, float inv_scale,
                                    int K, int T_in, int T_out, long long total)
{
    const long long idx = (long long)blockIdx.x * blockDim.x + threadIdx.x;
    if (idx >= total) return;
    const int row = (int)(idx / T_out);
    const int t   = (int)(idx - (long long)row * T_out);
    const float* p = u + (long long)row * T_in + t;
    float A = 0.f, B = 0.f;
    for (int m = 0; m < K; ++m) {
        const float x = p[m];
        A = fmaf(a, A, x);
        B = fmaf(b, B, x);
    }
    out[idx] = (a * A - b * B) * inv_scale;
}

extern "C" void kernel_launch(void* const* d_in, const int* in_sizes, int n_in,
                              void* d_out, int out_size)
{
    const float* u = (const float*)d_in[0];
    const int K = (n_in > 1) ? in_sizes[1] : 121;

    // rows * T_in = in_sizes[0]; rows * T_out = out_size; T_in - T_out = K - 1
    const long long total_in = (long long)in_sizes[0];
    int rows = 1;
    if (K > 1) {
        const long long diff = total_in - (long long)out_size;
        if (diff > 0 && diff % (K - 1) == 0) {
            const long long r = diff / (K - 1);
            if (r > 0 && total_in % r == 0 && out_size % r == 0) rows = (int)r;
        }
    }
    const int T_in  = (int)(total_in / rows);
    const int T_out = out_size / rows;

    // Constants from the reference formula (HZ=20, TAU1=1.0, TAU2=0.1)
    const double tau1 = 1.0 * 20.0;
    const double tau2 = 0.1 * 20.0;
    const double a = exp(-1.0 / tau1);
    const double b = exp(-1.0 / tau2);
    const double r = tau1 / tau2;
    const double d = tau1 - tau2;
    const double scale = pow(r, -tau2 / d) - pow(r, -tau1 / d);
    const double inv = 1.0 / scale;

    const float fa   = (float)a;
    const float fb   = (float)b;
    const float ia   = (float)(a * inv);                       // a/scale
    const float ib   = (float)(b * inv);                       // b/scale
    const float iaK1 = (float)(pow(a, (double)(K + 1)) * inv); // a^{K+1}/scale
    const float finv = (float)inv;
    const float l2a  = (float)(log(a) / log(2.0));
    const float l2b  = (float)(log(b) / log(2.0));

    const bool fast = (K >= 6) && ((K - 1) % 4 == 0) && (K - 1 <= 128) &&
                      (T_in % 4 == 0) && (T_out % 8 == 0);

    if (fast) {
        const int segs_per_row = (T_out + SEG_LEN - 1) / SEG_LEN;
        const int total_segs   = rows * segs_per_row;
        const int blocks = (total_segs + WARPS_PER_CTA - 1) / WARPS_PER_CTA;
        stc_scan_kernel<<<blocks, THREADS_SCAN>>>(
            u, (float*)d_out, fa, fb, ia, ib, iaK1, finv, l2a, l2b,
            K, T_in, T_out, segs_per_row, total_segs);
    } else {
        const long long total = (long long)rows * T_out;
        const int blocks = (int)((total + 255) / 256);
        stc_fallback_kernel<<<blocks, 256>>>(
            u, (float*)d_out, fa, fb, finv, K, T_in, T_out, total);
    }
}